// round 11
// baseline (speedup 1.0000x reference)
#include <cuda_runtime.h>
#include <cstdint>

// SAR-ADC 4-bit successive approximation quantizer.
// x: [500000, 24] f32 (12M elems), W: [10] f32.
// d_out: q [12M] f32 followed by Q [12M][4] f32.
//
// v7 = R7 best structure + L2::evict_first on the Q stream ONLY.
//   ptxas on sm_103a permits .L2::evict_* only on v8.b32/v4.b64 forms,
//   and Q is the only naturally-256-bit access. Marking the 192MB dead
//   Q stream evict-first makes it churn its own L2 lines instead of
//   evicting x (48MB, re-read every graph replay) and q (48MB,
//   rewritten in place) — those stay resident under normal policy.
//
// Layout (R7): warp owns 128 consecutive elements; thread t, step k
// handles pair e = warpBase + 64k + 2t. All accesses dense:
//   x LDG.64, q STG.64, Q STG.256 (evict_first).
//
// Compute: compare-direct thresholds — exactly equivalent to
//   sign(x - t + 1e-30): operands are O(0.1) so |x-t| is 0 or >= ~7e-9
//   >> 1e-30, and equality gives sign(+1e-30) = +1 = (x >= t).

#define VRf    0.1125f
#define VREFf  0.1125f

struct QR { float s0, s1, s2, s3, q; };

__device__ __forceinline__ QR quant1(
    float xx,
    float T3, float T2_0, float T2_1,
    float c1, float c1a, float c1b,
    float c0, float c0a, float c0b, float c0c)
{
    const bool  p3 = (xx >= T3);
    const float b3 = p3 ? 1.0f : 0.0f;
    const float t2 = p3 ? T2_1 : T2_0;

    const bool  p2 = (xx >= t2);
    const float b2 = p2 ? 1.0f : 0.0f;
    const float t1 = fmaf(b2, c1a, fmaf(b3, c1b, c1));

    const bool  p1 = (xx >= t1);
    const float b1 = p1 ? 1.0f : 0.0f;
    const float t0 = fmaf(b1, c0a, fmaf(b2, c0b, fmaf(b3, c0c, c0)));

    const bool  p0 = (xx >= t0);
    const float b0 = p0 ? 1.0f : 0.0f;

    QR r;
    r.s0 = p0 ? 1.0f : -1.0f;
    r.s1 = p1 ? 1.0f : -1.0f;
    r.s2 = p2 ? 1.0f : -1.0f;
    r.s3 = p3 ? 1.0f : -1.0f;
    float f = fmaf(b1, 2.0f, b0);
    f = fmaf(b2, 4.0f, f);
    f = fmaf(b3, 8.0f, f);
    r.q = f * VRf;
    return r;
}

__device__ __forceinline__ void stg256_ef(float* p,
    float a0, float a1, float a2, float a3,
    float a4, float a5, float a6, float a7)
{
    asm volatile(
        "st.global.L2::evict_first.v8.f32 [%0], {%1, %2, %3, %4, %5, %6, %7, %8};"
        :: "l"(p),
           "f"(a0), "f"(a1), "f"(a2), "f"(a3),
           "f"(a4), "f"(a5), "f"(a6), "f"(a7)
        : "memory");
}

__global__ __launch_bounds__(256) void sar_adc_kernel(
    const float* __restrict__ x,
    const float* __restrict__ W,
    float* __restrict__ q_out,   // 12M floats
    float* __restrict__ Q_out,   // 48M floats
    int n)                       // total elements; multiple of 128
{
    const int tid      = blockIdx.x * blockDim.x + threadIdx.x;
    const int warp_id  = tid >> 5;
    const int lane     = tid & 31;
    const int warpBase = warp_id << 7;        // 128 elements per warp

    if (warpBase >= n) return;                // n % 128 == 0: active warps full

    // Uniform weight loads (L1 broadcast).
    const float w0 = __ldg(&W[0]), w1 = __ldg(&W[1]), w2 = __ldg(&W[2]);
    const float w3 = __ldg(&W[3]), w4 = __ldg(&W[4]), w5 = __ldg(&W[5]);
    const float w6 = __ldg(&W[6]), w7 = __ldg(&W[7]), w8 = __ldg(&W[8]);
    const float w9 = __ldg(&W[9]);

    const float T3   = w9 * VREFf;
    const float T2_0 = w8 * VREFf;
    const float T2_1 = T2_0 + w7 * VRf;
    const float c1   = w6 * VREFf, c1a = w5 * VRf, c1b = w4 * VRf;
    const float c0   = w3 * VREFf, c0a = w2 * VRf, c0b = w1 * VRf, c0c = w0 * VRf;

    const int e0 = warpBase + 2 * lane;

    // Front-batch both pair loads (MLP=2; ample warp parallelism).
    float2 xv[2];
#pragma unroll
    for (int k = 0; k < 2; ++k)
        xv[k] = *reinterpret_cast<const float2*>(x + e0 + 64 * k);

#pragma unroll
    for (int k = 0; k < 2; ++k) {
        const int e = e0 + 64 * k;

        const QR a = quant1(xv[k].x, T3, T2_0, T2_1, c1, c1a, c1b, c0, c0a, c0b, c0c);
        const QR b = quant1(xv[k].y, T3, T2_0, T2_1, c1, c1a, c1b, c0, c0a, c0b, c0c);

        *reinterpret_cast<float2*>(q_out + e) = make_float2(a.q, b.q);

        stg256_ef(Q_out + (size_t)e * 4,
                  a.s0, a.s1, a.s2, a.s3,
                  b.s0, b.s1, b.s2, b.s3);
    }
}

extern "C" void kernel_launch(void* const* d_in, const int* in_sizes, int n_in,
                              void* d_out, int out_size) {
    const float* x = (const float*)d_in[0];
    const float* W = (const float*)d_in[1];

    const int n = in_sizes[0];            // 12,000,000 elements (multiple of 128)
    float* q_out = (float*)d_out;
    float* Q_out = (float*)d_out + n;

    const int threads = 256;
    const int elems_per_block = threads * 4;   // 1024 (128 per warp)
    const int blocks = (n + elems_per_block - 1) / elems_per_block;
    sar_adc_kernel<<<blocks, threads>>>(x, W, q_out, Q_out, n);
}

// round 13
// speedup vs baseline: 1.0121x; 1.0121x over previous
#include <cuda_runtime.h>
#include <cstdint>

// SAR-ADC 4-bit successive approximation quantizer.
// x: [500000, 24] f32 (12M elems), W: [10] f32.
// d_out: q [12M] f32 followed by Q [12M][4] f32.
//
// v8 = R7 best structure + L2 residency tagging for the graph-replay loop:
//   - x lines tagged via prefetch.global.L2::evict_last (one per 128B line
//     per warp, predicated on lane%16==0). 48MB x working set < 126MB L2,
//     so across replays x reads become L2 hits (saves ~48MB DRAM/iter).
//   - Q stream: st.global.L2::evict_first.v8 (192MB dead stream evicts its
//     own lines first instead of churning x/q).
//   - q: plain STG.64 (rewritten in place each replay; L2-absorbed).
//
// Layout (R7): warp owns 128 consecutive elements; thread t, step k
// handles pair e = warpBase + 64k + 2t. All accesses dense across the
// warp: x LDG.64, q STG.64, Q STG.256.
//
// Compute: compare-direct thresholds — exactly equivalent to
//   sign(x - t + 1e-30): operands are O(0.1) so |x-t| is 0 or >= ~7e-9
//   >> 1e-30, and equality gives sign(+1e-30) = +1 = (x >= t).

#define VRf    0.1125f
#define VREFf  0.1125f

struct QR { float s0, s1, s2, s3, q; };

__device__ __forceinline__ QR quant1(
    float xx,
    float T3, float T2_0, float T2_1,
    float c1, float c1a, float c1b,
    float c0, float c0a, float c0b, float c0c)
{
    const bool  p3 = (xx >= T3);
    const float b3 = p3 ? 1.0f : 0.0f;
    const float t2 = p3 ? T2_1 : T2_0;

    const bool  p2 = (xx >= t2);
    const float b2 = p2 ? 1.0f : 0.0f;
    const float t1 = fmaf(b2, c1a, fmaf(b3, c1b, c1));

    const bool  p1 = (xx >= t1);
    const float b1 = p1 ? 1.0f : 0.0f;
    const float t0 = fmaf(b1, c0a, fmaf(b2, c0b, fmaf(b3, c0c, c0)));

    const bool  p0 = (xx >= t0);
    const float b0 = p0 ? 1.0f : 0.0f;

    QR r;
    r.s0 = p0 ? 1.0f : -1.0f;
    r.s1 = p1 ? 1.0f : -1.0f;
    r.s2 = p2 ? 1.0f : -1.0f;
    r.s3 = p3 ? 1.0f : -1.0f;
    float f = fmaf(b1, 2.0f, b0);
    f = fmaf(b2, 4.0f, f);
    f = fmaf(b3, 8.0f, f);
    r.q = f * VRf;
    return r;
}

__device__ __forceinline__ void prefetch_l2_last(const float* p) {
    asm volatile("prefetch.global.L2::evict_last [%0];" :: "l"(p));
}

__device__ __forceinline__ void stg256_ef(float* p,
    float a0, float a1, float a2, float a3,
    float a4, float a5, float a6, float a7)
{
    asm volatile(
        "st.global.L2::evict_first.v8.f32 [%0], {%1, %2, %3, %4, %5, %6, %7, %8};"
        :: "l"(p),
           "f"(a0), "f"(a1), "f"(a2), "f"(a3),
           "f"(a4), "f"(a5), "f"(a6), "f"(a7)
        : "memory");
}

__global__ __launch_bounds__(256) void sar_adc_kernel(
    const float* __restrict__ x,
    const float* __restrict__ W,
    float* __restrict__ q_out,   // 12M floats
    float* __restrict__ Q_out,   // 48M floats
    int n)                       // total elements; multiple of 128
{
    const int tid      = blockIdx.x * blockDim.x + threadIdx.x;
    const int warp_id  = tid >> 5;
    const int lane     = tid & 31;
    const int warpBase = warp_id << 7;        // 128 elements per warp

    if (warpBase >= n) return;                // n % 128 == 0: active warps full

    const int e0 = warpBase + 2 * lane;

    // Tag the 4 x-lines this warp touches as L2 evict_last (one prefetch
    // per 128B line: lanes 0 and 16 sit exactly at line starts).
    if ((lane & 15) == 0) {
        prefetch_l2_last(x + e0);        // lines 0 (lane 0) and 1 (lane 16)
        prefetch_l2_last(x + e0 + 64);   // lines 2 and 3
    }

    // Uniform weight loads (L1 broadcast).
    const float w0 = __ldg(&W[0]), w1 = __ldg(&W[1]), w2 = __ldg(&W[2]);
    const float w3 = __ldg(&W[3]), w4 = __ldg(&W[4]), w5 = __ldg(&W[5]);
    const float w6 = __ldg(&W[6]), w7 = __ldg(&W[7]), w8 = __ldg(&W[8]);
    const float w9 = __ldg(&W[9]);

    const float T3   = w9 * VREFf;
    const float T2_0 = w8 * VREFf;
    const float T2_1 = T2_0 + w7 * VRf;
    const float c1   = w6 * VREFf, c1a = w5 * VRf, c1b = w4 * VRf;
    const float c0   = w3 * VREFf, c0a = w2 * VRf, c0b = w1 * VRf, c0c = w0 * VRf;

    // Front-batch both pair loads (MLP=2; ample warp parallelism).
    float2 xv[2];
#pragma unroll
    for (int k = 0; k < 2; ++k)
        xv[k] = *reinterpret_cast<const float2*>(x + e0 + 64 * k);

#pragma unroll
    for (int k = 0; k < 2; ++k) {
        const int e = e0 + 64 * k;

        const QR a = quant1(xv[k].x, T3, T2_0, T2_1, c1, c1a, c1b, c0, c0a, c0b, c0c);
        const QR b = quant1(xv[k].y, T3, T2_0, T2_1, c1, c1a, c1b, c0, c0a, c0b, c0c);

        *reinterpret_cast<float2*>(q_out + e) = make_float2(a.q, b.q);

        stg256_ef(Q_out + (size_t)e * 4,
                  a.s0, a.s1, a.s2, a.s3,
                  b.s0, b.s1, b.s2, b.s3);
    }
}

extern "C" void kernel_launch(void* const* d_in, const int* in_sizes, int n_in,
                              void* d_out, int out_size) {
    const float* x = (const float*)d_in[0];
    const float* W = (const float*)d_in[1];

    const int n = in_sizes[0];            // 12,000,000 elements (multiple of 128)
    float* q_out = (float*)d_out;
    float* Q_out = (float*)d_out + n;

    const int threads = 256;
    const int elems_per_block = threads * 4;   // 1024 (128 per warp)
    const int blocks = (n + elems_per_block - 1) / elems_per_block;
    sar_adc_kernel<<<blocks, threads>>>(x, W, q_out, Q_out, n);
}